// round 6
// baseline (speedup 1.0000x reference)
#include <cuda_runtime.h>
#include <cuda_bf16.h>
#include <math.h>

// ContextVAE fused kernel: fp32 packed f32x2 (FFMA2), M=2 elements/thread,
// message stage j-split into two 20-wide passes (low half parked in shared
// scratch) so peak regs fit 2 blocks/SM (4 warps/SMSP).

#define BATCH 262144
#define HALF_B (BATCH/2)
#define NTHREADS 256

typedef unsigned long long u64;

__device__ __forceinline__ u64 f2fma(u64 a, u64 b, u64 c) {
    u64 d;
    asm("fma.rn.f32x2 %0, %1, %2, %3;" : "=l"(d) : "l"(a), "l"(b), "l"(c));
    return d;
}
__device__ __forceinline__ u64 f2add(u64 a, u64 b) {
    u64 d;
    asm("add.rn.f32x2 %0, %1, %2;" : "=l"(d) : "l"(a), "l"(b));
    return d;
}
__device__ __forceinline__ u64 f2pack(float lo, float hi) {
    u64 r;
    asm("mov.b64 %0, {%1, %2};" : "=l"(r) : "f"(lo), "f"(hi));
    return r;
}
__device__ __forceinline__ u64 f2dup(float v) {
    u64 r;
    asm("mov.b64 %0, {%1, %1};" : "=l"(r) : "f"(v));
    return r;
}
__device__ __forceinline__ float2 f2unpack(u64 p) {
    float2 r;
    asm("mov.b64 {%0, %1}, %2;" : "=f"(r.x), "=f"(r.y) : "l"(p));
    return r;
}

// Shared layout (floats), 16B-aligned blocks:
//  sW1e  [4*128*4]   : per edge e, neuron o: {W1[o,10], W1[o,11], W1[o,12], b1[o]+W1[o,0]+W1[o,6+e]}
//  sW2P  [2*128*20]  : pass p, row k: W2[20p+j, k] for j<20 (0-padded at j=39)
//  sW3   [128*40]    : row j: W3[j,k] k<39, [39]=b3[j]
//  sWmv  [128*16]    : row j: {Wm[0..7,j], Wv[0..7,j]}
//  sWd1  [32*24]     : row h: {Wd1[h,5..16], Wd1[h,17..24], bd1[h]+Wd1[h,0], 0,0,0}
//  sWd2  [32*12]     : row h: Wd2[0..11,h]
//  sBmv [16], sBd2 [12], sB2 [40]
//  sMS   [2*10*256]  u64 scratch: per-thread parked msum-low halves
#define OFF_W1E  0
#define OFF_W2P  (OFF_W1E + 4*128*4)
#define OFF_W3   (OFF_W2P + 2*128*20)
#define OFF_WMV  (OFF_W3  + 128*40)
#define OFF_WD1  (OFF_WMV + 128*16)
#define OFF_WD2  (OFF_WD1 + 32*24)
#define OFF_BMV  (OFF_WD2 + 32*12)
#define OFF_BD2  (OFF_BMV + 16)
#define OFF_B2   (OFF_BD2 + 12)
#define OFF_MS   (OFF_B2 + 40)            // u64-aligned (index is even)
#define SMEM_FLOATS (OFF_MS + 2*10*256*2)
#define SMEM_BYTES  (SMEM_FLOATS * 4)

__global__ __launch_bounds__(NTHREADS, 2)
void vae_kernel(const float* __restrict__ initial_c,
                const float* __restrict__ current_c,
                const float* __restrict__ eps,
                const float* __restrict__ W1, const float* __restrict__ b1,
                const float* __restrict__ W2, const float* __restrict__ b2,
                const float* __restrict__ W3, const float* __restrict__ b3,
                const float* __restrict__ Wm, const float* __restrict__ bm,
                const float* __restrict__ Wv, const float* __restrict__ bv,
                const float* __restrict__ Wd1, const float* __restrict__ bd1,
                const float* __restrict__ Wd2, const float* __restrict__ bd2,
                float* __restrict__ out)
{
    extern __shared__ float sm[];
    float* sW1e = sm + OFF_W1E;
    float* sW2P = sm + OFF_W2P;
    float* sW3  = sm + OFF_W3;
    float* sWmv = sm + OFF_WMV;
    float* sWd1 = sm + OFF_WD1;
    float* sWd2 = sm + OFF_WD2;
    float* sBmv = sm + OFF_BMV;
    float* sBd2 = sm + OFF_BD2;
    float* sB2  = sm + OFF_B2;
    u64*   sMS  = (u64*)(sm + OFF_MS);

    const int t = threadIdx.x;

    // ---- pack weights into shared ----
    for (int i = t; i < 4*128; i += NTHREADS) {
        int e = i >> 7, o = i & 127;
        float4 v;
        v.x = __ldg(&W1[o*13 + 10]);
        v.y = __ldg(&W1[o*13 + 11]);
        v.z = __ldg(&W1[o*13 + 12]);
        v.w = __ldg(&b1[o]) + __ldg(&W1[o*13 + 0]) + __ldg(&W1[o*13 + 6 + e]);
        ((float4*)sW1e)[i] = v;
    }
    for (int i = t; i < 2*128*20; i += NTHREADS) {
        int p = i / (128*20);
        int r = i % (128*20);
        int k = r / 20, j = r % 20;
        int jj = 20*p + j;
        sW2P[i] = (jj < 39) ? __ldg(&W2[jj*128 + k]) : 0.f;
    }
    for (int i = t; i < 128*40; i += NTHREADS) {
        int j = i / 40, k = i % 40;
        sW3[i] = (k < 39) ? __ldg(&W3[j*39 + k]) : __ldg(&b3[j]);
    }
    for (int i = t; i < 128*16; i += NTHREADS) {
        int j = i / 16, q = i % 16;
        sWmv[i] = (q < 8) ? __ldg(&Wm[q*128 + j]) : __ldg(&Wv[(q-8)*128 + j]);
    }
    for (int i = t; i < 32*24; i += NTHREADS) {
        int h = i / 24, q = i % 24;
        float v;
        if (q < 12)       v = __ldg(&Wd1[h*25 + 5 + q]);
        else if (q < 20)  v = __ldg(&Wd1[h*25 + 17 + (q-12)]);
        else if (q == 20) v = __ldg(&bd1[h]) + __ldg(&Wd1[h*25 + 0]);
        else              v = 0.f;
        sWd1[i] = v;
    }
    for (int i = t; i < 32*12; i += NTHREADS) {
        int h = i / 12, j = i % 12;
        sWd2[i] = __ldg(&Wd2[j*32 + h]);
    }
    if (t < 16) sBmv[t] = (t < 8) ? __ldg(&bm[t]) : __ldg(&bv[t-8]);
    if (t < 12) sBd2[t] = __ldg(&bd2[t]);
    if (t < 40) sB2[t]  = (t < 39) ? __ldg(&b2[t]) : 0.f;
    __syncthreads();

    const int b0 = blockIdx.x * NTHREADS + t;
    const int b1i = b0 + HALF_B;
    const float* cc0 = current_c + (size_t)b0  * 30;
    const float* cc1 = current_c + (size_t)b1i * 30;

    float curA[12], curB[12];
    #pragma unroll
    for (int e = 0; e < 4; e++) {
        curA[3*e+0] = __ldg(&cc0[e]);
        curA[3*e+1] = __ldg(&cc0[10 + e]);
        curA[3*e+2] = __ldg(&cc0[14 + 4*e]);
        curB[3*e+0] = __ldg(&cc1[e]);
        curB[3*e+1] = __ldg(&cc1[10 + e]);
        curB[3*e+2] = __ldg(&cc1[14 + 4*e]);
    }

    // ================= message stage, pass 0 (outputs j 0..19) =================
    u64 mA[10], mB[10];
    #pragma unroll
    for (int q = 0; q < 10; q++) { mA[q] = 0ULL; mB[q] = 0ULL; }

    #pragma unroll 1
    for (int e = 0; e < 4; e++) {
        const float pA0 = curA[3*e], pA1 = curA[3*e+1], pA2 = curA[3*e+2];
        const float pB0 = curB[3*e], pB1 = curB[3*e+1], pB2 = curB[3*e+2];
        const float4* w1 = (const float4*)(sW1e) + e*128;

        u64 a0[10], a1[10];
        {
            const ulonglong2* bb = (const ulonglong2*)sB2;   // first 20 floats
            #pragma unroll
            for (int q = 0; q < 5; q++) {
                ulonglong2 v = bb[q];
                a0[2*q] = v.x; a0[2*q+1] = v.y;
                a1[2*q] = v.x; a1[2*q+1] = v.y;
            }
        }
        #pragma unroll 2
        for (int k = 0; k < 128; k++) {
            float4 w = w1[k];
            float xA = fmaxf(fmaf(w.x, pA0, fmaf(w.y, pA1, fmaf(w.z, pA2, w.w))), 0.f);
            float xB = fmaxf(fmaf(w.x, pB0, fmaf(w.y, pB1, fmaf(w.z, pB2, w.w))), 0.f);
            u64 dA = f2dup(xA);
            u64 dB = f2dup(xB);
            const ulonglong2* crow = (const ulonglong2*)(sW2P + k*20);
            #pragma unroll
            for (int q = 0; q < 5; q++) {
                ulonglong2 c = crow[q];
                a0[2*q]   = f2fma(c.x, dA, a0[2*q]);
                a0[2*q+1] = f2fma(c.y, dA, a0[2*q+1]);
                a1[2*q]   = f2fma(c.x, dB, a1[2*q]);
                a1[2*q+1] = f2fma(c.y, dB, a1[2*q+1]);
            }
        }
        #pragma unroll
        for (int q = 0; q < 10; q++) {
            float2 u0 = f2unpack(a0[q]);
            float2 u1 = f2unpack(a1[q]);
            mA[q] = f2add(mA[q], f2pack(fmaxf(u0.x, 0.f), fmaxf(u0.y, 0.f)));
            mB[q] = f2add(mB[q], f2pack(fmaxf(u1.x, 0.f), fmaxf(u1.y, 0.f)));
        }
    }
    // park low halves in shared scratch (private slots, conflict-free)
    #pragma unroll
    for (int q = 0; q < 10; q++) {
        sMS[q*NTHREADS + t]                 = mA[q];
        sMS[(10+q)*NTHREADS + t]            = mB[q];
    }

    // ================= message stage, pass 1 (outputs j 20..39) =================
    #pragma unroll
    for (int q = 0; q < 10; q++) { mA[q] = 0ULL; mB[q] = 0ULL; }

    #pragma unroll 1
    for (int e = 0; e < 4; e++) {
        const float pA0 = curA[3*e], pA1 = curA[3*e+1], pA2 = curA[3*e+2];
        const float pB0 = curB[3*e], pB1 = curB[3*e+1], pB2 = curB[3*e+2];
        const float4* w1 = (const float4*)(sW1e) + e*128;

        u64 a0[10], a1[10];
        {
            const ulonglong2* bb = (const ulonglong2*)(sB2 + 20);
            #pragma unroll
            for (int q = 0; q < 5; q++) {
                ulonglong2 v = bb[q];
                a0[2*q] = v.x; a0[2*q+1] = v.y;
                a1[2*q] = v.x; a1[2*q+1] = v.y;
            }
        }
        #pragma unroll 2
        for (int k = 0; k < 128; k++) {
            float4 w = w1[k];
            float xA = fmaxf(fmaf(w.x, pA0, fmaf(w.y, pA1, fmaf(w.z, pA2, w.w))), 0.f);
            float xB = fmaxf(fmaf(w.x, pB0, fmaf(w.y, pB1, fmaf(w.z, pB2, w.w))), 0.f);
            u64 dA = f2dup(xA);
            u64 dB = f2dup(xB);
            const ulonglong2* crow = (const ulonglong2*)(sW2P + (128 + k)*20);
            #pragma unroll
            for (int q = 0; q < 5; q++) {
                ulonglong2 c = crow[q];
                a0[2*q]   = f2fma(c.x, dA, a0[2*q]);
                a0[2*q+1] = f2fma(c.y, dA, a0[2*q+1]);
                a1[2*q]   = f2fma(c.x, dB, a1[2*q]);
                a1[2*q+1] = f2fma(c.y, dB, a1[2*q+1]);
            }
        }
        #pragma unroll
        for (int q = 0; q < 10; q++) {
            float2 u0 = f2unpack(a0[q]);
            float2 u1 = f2unpack(a1[q]);
            mA[q] = f2add(mA[q], f2pack(fmaxf(u0.x, 0.f), fmaxf(u0.y, 0.f)));
            mB[q] = f2add(mB[q], f2pack(fmaxf(u1.x, 0.f), fmaxf(u1.y, 0.f)));
        }
    }

    // assemble full msum: ms[0..9] from scratch, ms[10..19] = pass-1 regs
    u64 ms0[20], ms1[20];
    #pragma unroll
    for (int q = 0; q < 10; q++) {
        ms0[q]    = sMS[q*NTHREADS + t];
        ms1[q]    = sMS[(10+q)*NTHREADS + t];
        ms0[10+q] = mA[q];
        ms1[10+q] = mB[q];
    }
    // bias trick: element 39 pairs with W3 row's [39] = b3[j]
    {
        float2 v0 = f2unpack(ms0[19]);
        float2 v1 = f2unpack(ms1[19]);
        ms0[19] = f2pack(v0.x, 1.0f);
        ms1[19] = f2pack(v1.x, 1.0f);
    }

    // ---- readout: 39(+1) -> 128 relu -> means/log_var, weights shared ----
    u64 mv0[8], mv1[8];
    {
        const ulonglong2* bb = (const ulonglong2*)sBmv;
        #pragma unroll
        for (int q = 0; q < 4; q++) {
            ulonglong2 v = bb[q];
            mv0[2*q] = v.x; mv0[2*q+1] = v.y;
            mv1[2*q] = v.x; mv1[2*q+1] = v.y;
        }
    }

    #pragma unroll 2
    for (int j = 0; j < 128; j++) {
        const ulonglong2* w3r = (const ulonglong2*)(sW3 + j*40);
        u64 s0 = 0ULL, s1 = 0ULL, r0 = 0ULL, r1 = 0ULL;
        #pragma unroll
        for (int q = 0; q < 10; q += 2) {
            ulonglong2 c0 = w3r[q];
            ulonglong2 c1 = w3r[q+1];
            s0 = f2fma(c0.x, ms0[2*q],   s0);
            s1 = f2fma(c0.y, ms0[2*q+1], s1);
            s0 = f2fma(c1.x, ms0[2*q+2], s0);
            s1 = f2fma(c1.y, ms0[2*q+3], s1);
            r0 = f2fma(c0.x, ms1[2*q],   r0);
            r1 = f2fma(c0.y, ms1[2*q+1], r1);
            r0 = f2fma(c1.x, ms1[2*q+2], r0);
            r1 = f2fma(c1.y, ms1[2*q+3], r1);
        }
        float2 uA = f2unpack(f2add(s0, s1));
        float2 uB = f2unpack(f2add(r0, r1));
        float x3A = fmaxf(uA.x + uA.y, 0.f);
        float x3B = fmaxf(uB.x + uB.y, 0.f);
        u64 xpA = f2dup(x3A);
        u64 xpB = f2dup(x3B);
        const ulonglong2* wm = (const ulonglong2*)(sWmv + j*16);
        #pragma unroll
        for (int q = 0; q < 4; q++) {
            ulonglong2 c = wm[q];
            mv0[2*q]   = f2fma(c.x, xpA, mv0[2*q]);
            mv0[2*q+1] = f2fma(c.y, xpA, mv0[2*q+1]);
            mv1[2*q]   = f2fma(c.x, xpB, mv1[2*q]);
            mv1[2*q+1] = f2fma(c.y, xpB, mv1[2*q+1]);
        }
    }

    // ---- reparameterization ----
    float mvsA[16], mvsB[16];
    #pragma unroll
    for (int q = 0; q < 8; q++) {
        float2 vA = f2unpack(mv0[q]);
        float2 vB = f2unpack(mv1[q]);
        mvsA[2*q] = vA.x; mvsA[2*q+1] = vA.y;
        mvsB[2*q] = vB.x; mvsB[2*q+1] = vB.y;
    }
    float zvA[8], zvB[8];
    {
        const float4* epv = (const float4*)(eps + (size_t)b0 * 8);
        float4 e0 = epv[0], e1 = epv[1];
        float ev[8] = {e0.x, e0.y, e0.z, e0.w, e1.x, e1.y, e1.z, e1.w};
        #pragma unroll
        for (int i = 0; i < 8; i++)
            zvA[i] = fmaf(ev[i], __expf(0.5f * mvsA[8+i]), mvsA[i]);
    }
    {
        const float4* epv = (const float4*)(eps + (size_t)b1i * 8);
        float4 e0 = epv[0], e1 = epv[1];
        float ev[8] = {e0.x, e0.y, e0.z, e0.w, e1.x, e1.y, e1.z, e1.w};
        #pragma unroll
        for (int i = 0; i < 8; i++)
            zvB[i] = fmaf(ev[i], __expf(0.5f * mvsB[8+i]), mvsB[i]);
    }

    // ---- decoder: weights shared between both elements ----
    const float* ic0 = initial_c + (size_t)b0  * 30;
    const float* ic1 = initial_c + (size_t)b1i * 30;
    u64 dA[12], dB[12];
    dA[0] = f2pack(__ldg(&ic0[0]),  __ldg(&ic0[1]));
    dA[1] = f2pack(__ldg(&ic0[2]),  __ldg(&ic0[3]));
    dA[2] = f2pack(__ldg(&ic0[10]), __ldg(&ic0[11]));
    dA[3] = f2pack(__ldg(&ic0[12]), __ldg(&ic0[13]));
    dA[4] = f2pack(__ldg(&ic0[14]), __ldg(&ic0[18]));
    dA[5] = f2pack(__ldg(&ic0[22]), __ldg(&ic0[26]));
    dA[6] = f2pack(zvA[0], zvA[1]);
    dA[7] = f2pack(zvA[2], zvA[3]);
    dA[8] = f2pack(zvA[4], zvA[5]);
    dA[9] = f2pack(zvA[6], zvA[7]);
    dA[10] = f2pack(1.f, 0.f);
    dA[11] = 0ULL;
    dB[0] = f2pack(__ldg(&ic1[0]),  __ldg(&ic1[1]));
    dB[1] = f2pack(__ldg(&ic1[2]),  __ldg(&ic1[3]));
    dB[2] = f2pack(__ldg(&ic1[10]), __ldg(&ic1[11]));
    dB[3] = f2pack(__ldg(&ic1[12]), __ldg(&ic1[13]));
    dB[4] = f2pack(__ldg(&ic1[14]), __ldg(&ic1[18]));
    dB[5] = f2pack(__ldg(&ic1[22]), __ldg(&ic1[26]));
    dB[6] = f2pack(zvB[0], zvB[1]);
    dB[7] = f2pack(zvB[2], zvB[3]);
    dB[8] = f2pack(zvB[4], zvB[5]);
    dB[9] = f2pack(zvB[6], zvB[7]);
    dB[10] = f2pack(1.f, 0.f);
    dB[11] = 0ULL;

    u64 rA[6], rB[6];
    {
        const ulonglong2* bb = (const ulonglong2*)sBd2;
        #pragma unroll
        for (int q = 0; q < 3; q++) {
            ulonglong2 v = bb[q];
            rA[2*q] = v.x; rA[2*q+1] = v.y;
            rB[2*q] = v.x; rB[2*q+1] = v.y;
        }
    }

    #pragma unroll 4
    for (int h = 0; h < 32; h++) {
        const ulonglong2* w1r = (const ulonglong2*)(sWd1 + h*24);
        u64 t0 = 0ULL, t1 = 0ULL, u0 = 0ULL, u1 = 0ULL;
        #pragma unroll
        for (int q = 0; q < 6; q += 2) {
            ulonglong2 c0 = w1r[q];
            ulonglong2 c1 = w1r[q+1];
            t0 = f2fma(c0.x, dA[2*q],   t0);
            t1 = f2fma(c0.y, dA[2*q+1], t1);
            t0 = f2fma(c1.x, dA[2*q+2], t0);
            t1 = f2fma(c1.y, dA[2*q+3], t1);
            u0 = f2fma(c0.x, dB[2*q],   u0);
            u1 = f2fma(c0.y, dB[2*q+1], u1);
            u0 = f2fma(c1.x, dB[2*q+2], u0);
            u1 = f2fma(c1.y, dB[2*q+3], u1);
        }
        float2 sA = f2unpack(f2add(t0, t1));
        float2 sB = f2unpack(f2add(u0, u1));
        float hvA = fmaxf(sA.x + sA.y, 0.f);
        float hvB = fmaxf(sB.x + sB.y, 0.f);
        u64 hpA = f2dup(hvA);
        u64 hpB = f2dup(hvB);
        const ulonglong2* w2r = (const ulonglong2*)(sWd2 + h*12);
        #pragma unroll
        for (int q = 0; q < 3; q++) {
            ulonglong2 c = w2r[q];
            rA[2*q]   = f2fma(c.x, hpA, rA[2*q]);
            rA[2*q+1] = f2fma(c.y, hpA, rA[2*q+1]);
            rB[2*q]   = f2fma(c.x, hpB, rB[2*q]);
            rB[2*q+1] = f2fma(c.y, hpB, rB[2*q+1]);
        }
    }

    // ---- stores: recon_x [B,12] | means [B,8] | log_var [B,8] | z [B,8] ----
    {
        float rr[12];
        #pragma unroll
        for (int q = 0; q < 6; q++) {
            float2 v = f2unpack(rA[q]);
            rr[2*q] = v.x; rr[2*q+1] = v.y;
        }
        float* out_rec = out + (size_t)b0 * 12;
        #pragma unroll
        for (int ii = 0; ii < 3; ii++) {
            float4 v;
            v.x = __fdividef(1.f, 1.f + __expf(-rr[ii*4+0]));
            v.y = __fdividef(1.f, 1.f + __expf(-rr[ii*4+1]));
            v.z = __fdividef(1.f, 1.f + __expf(-rr[ii*4+2]));
            v.w = __fdividef(1.f, 1.f + __expf(-rr[ii*4+3]));
            ((float4*)out_rec)[ii] = v;
        }
        float* out_mean = out + (size_t)12*BATCH + (size_t)b0*8;
        ((float4*)out_mean)[0] = make_float4(mvsA[0], mvsA[1], mvsA[2], mvsA[3]);
        ((float4*)out_mean)[1] = make_float4(mvsA[4], mvsA[5], mvsA[6], mvsA[7]);
        float* out_lv = out + (size_t)20*BATCH + (size_t)b0*8;
        ((float4*)out_lv)[0] = make_float4(mvsA[8],  mvsA[9],  mvsA[10], mvsA[11]);
        ((float4*)out_lv)[1] = make_float4(mvsA[12], mvsA[13], mvsA[14], mvsA[15]);
        float* out_z = out + (size_t)28*BATCH + (size_t)b0*8;
        ((float4*)out_z)[0] = make_float4(zvA[0], zvA[1], zvA[2], zvA[3]);
        ((float4*)out_z)[1] = make_float4(zvA[4], zvA[5], zvA[6], zvA[7]);
    }
    {
        float rr[12];
        #pragma unroll
        for (int q = 0; q < 6; q++) {
            float2 v = f2unpack(rB[q]);
            rr[2*q] = v.x; rr[2*q+1] = v.y;
        }
        float* out_rec = out + (size_t)b1i * 12;
        #pragma unroll
        for (int ii = 0; ii < 3; ii++) {
            float4 v;
            v.x = __fdividef(1.f, 1.f + __expf(-rr[ii*4+0]));
            v.y = __fdividef(1.f, 1.f + __expf(-rr[ii*4+1]));
            v.z = __fdividef(1.f, 1.f + __expf(-rr[ii*4+2]));
            v.w = __fdividef(1.f, 1.f + __expf(-rr[ii*4+3]));
            ((float4*)out_rec)[ii] = v;
        }
        float* out_mean = out + (size_t)12*BATCH + (size_t)b1i*8;
        ((float4*)out_mean)[0] = make_float4(mvsB[0], mvsB[1], mvsB[2], mvsB[3]);
        ((float4*)out_mean)[1] = make_float4(mvsB[4], mvsB[5], mvsB[6], mvsB[7]);
        float* out_lv = out + (size_t)20*BATCH + (size_t)b1i*8;
        ((float4*)out_lv)[0] = make_float4(mvsB[8],  mvsB[9],  mvsB[10], mvsB[11]);
        ((float4*)out_lv)[1] = make_float4(mvsB[12], mvsB[13], mvsB[14], mvsB[15]);
        float* out_z = out + (size_t)28*BATCH + (size_t)b1i*8;
        ((float4*)out_z)[0] = make_float4(zvB[0], zvB[1], zvB[2], zvB[3]);
        ((float4*)out_z)[1] = make_float4(zvB[4], zvB[5], zvB[6], zvB[7]);
    }
}

extern "C" void kernel_launch(void* const* d_in, const int* in_sizes, int n_in,
                              void* d_out, int out_size)
{
    const float* initial_c = (const float*)d_in[0];
    // d_in[1] = initial_s (unused)
    const float* current_c = (const float*)d_in[2];
    const float* eps       = (const float*)d_in[3];
    const float* W1  = (const float*)d_in[4];
    const float* b1  = (const float*)d_in[5];
    const float* W2  = (const float*)d_in[6];
    const float* b2  = (const float*)d_in[7];
    const float* W3  = (const float*)d_in[8];
    const float* b3  = (const float*)d_in[9];
    const float* Wm  = (const float*)d_in[10];
    const float* bm  = (const float*)d_in[11];
    const float* Wv  = (const float*)d_in[12];
    const float* bv  = (const float*)d_in[13];
    const float* Wd1 = (const float*)d_in[14];
    const float* bd1 = (const float*)d_in[15];
    const float* Wd2 = (const float*)d_in[16];
    const float* bd2 = (const float*)d_in[17];
    float* out = (float*)d_out;

    cudaFuncSetAttribute(vae_kernel, cudaFuncAttributeMaxDynamicSharedMemorySize, SMEM_BYTES);
    vae_kernel<<<HALF_B / NTHREADS, NTHREADS, SMEM_BYTES>>>(
        initial_c, current_c, eps,
        W1, b1, W2, b2, W3, b3, Wm, bm, Wv, bv, Wd1, bd1, Wd2, bd2,
        out);
}

// round 7
// speedup vs baseline: 1.1742x; 1.1742x over previous
#include <cuda_runtime.h>
#include <cuda_bf16.h>
#include <math.h>

// ContextVAE fused kernel: fp32 packed f32x2 (FFMA2), M=2 elements/thread,
// 4 edges processed JOINTLY (one W2 row load feeds 8 accumulator chains),
// j-dim split into two 20-wide passes; pass-0 half parked in smem scratch.

#define BATCH 262144
#define HALF_B (BATCH/2)
#define NTHREADS 256

typedef unsigned long long u64;

__device__ __forceinline__ u64 f2fma(u64 a, u64 b, u64 c) {
    u64 d;
    asm("fma.rn.f32x2 %0, %1, %2, %3;" : "=l"(d) : "l"(a), "l"(b), "l"(c));
    return d;
}
__device__ __forceinline__ u64 f2add(u64 a, u64 b) {
    u64 d;
    asm("add.rn.f32x2 %0, %1, %2;" : "=l"(d) : "l"(a), "l"(b));
    return d;
}
__device__ __forceinline__ u64 f2pack(float lo, float hi) {
    u64 r;
    asm("mov.b64 %0, {%1, %2};" : "=l"(r) : "f"(lo), "f"(hi));
    return r;
}
__device__ __forceinline__ u64 f2dup(float v) {
    u64 r;
    asm("mov.b64 %0, {%1, %1};" : "=l"(r) : "f"(v));
    return r;
}
__device__ __forceinline__ float2 f2unpack(u64 p) {
    float2 r;
    asm("mov.b64 {%0, %1}, %2;" : "=f"(r.x), "=f"(r.y) : "l"(p));
    return r;
}

// Shared layout (floats):
//  sW1w [128*4]   : per k: {W1[k,10], W1[k,11], W1[k,12], 0}   (same for all edges)
//  sW1b [128*4]   : per k: {bias_e0, bias_e1, bias_e2, bias_e3}, bias_e = b1+W1[,0]+W1[,6+e]
//  sW2H [2*128*20]: pass p, row k: W2[20p+j, k] for j<20 (0-pad at j=39)
//  sW3  [128*40]  : row j: W3[j,k] k<39, [39]=b3[j]
//  sWmv [128*16]  : row j: {Wm[0..7,j], Wv[0..7,j]}
//  sWd1 [32*24]   : row h: {Wd1[h,5..16], Wd1[h,17..24], bd1[h]+Wd1[h,0], 0,0,0}
//  sWd2 [32*12]   : row h: Wd2[0..11,h]
//  sBmv [16], sBd2 [12], sB2 [40]
//  sMS  u64[20*256] scratch: parked pass-0 msum halves (elemA q0..9, elemB q10..19)
#define OFF_W1W  0
#define OFF_W1B  (OFF_W1W + 128*4)
#define OFF_W2H  (OFF_W1B + 128*4)
#define OFF_W3   (OFF_W2H + 2*128*20)
#define OFF_WMV  (OFF_W3  + 128*40)
#define OFF_WD1  (OFF_WMV + 128*16)
#define OFF_WD2  (OFF_WD1 + 32*24)
#define OFF_BMV  (OFF_WD2 + 32*12)
#define OFF_BD2  (OFF_BMV + 16)
#define OFF_B2   (OFF_BD2 + 12)
#define OFF_MS   (OFF_B2 + 40)            // even index -> u64 aligned
#define SMEM_FLOATS (OFF_MS + 20*256*2)
#define SMEM_BYTES  (SMEM_FLOATS * 4)

// One j-half (20 outputs) of the message stage for all 4 edges x 2 elements.
__device__ __forceinline__ void message_half(
    const float* __restrict__ sW1w, const float* __restrict__ sW1b,
    const float* __restrict__ sW2Hp, const float* __restrict__ sB2h,
    const float* __restrict__ curA, const float* __restrict__ curB,
    u64* __restrict__ msA, u64* __restrict__ msB)
{
    u64 acc[8][10];
    {
        const ulonglong2* bb = (const ulonglong2*)sB2h;
        u64 binit[10];
        #pragma unroll
        for (int q = 0; q < 5; q++) {
            ulonglong2 v = bb[q];
            binit[2*q] = v.x; binit[2*q+1] = v.y;
        }
        #pragma unroll
        for (int em = 0; em < 8; em++)
            #pragma unroll
            for (int q = 0; q < 10; q++)
                acc[em][q] = binit[q];
    }

    const float4* w4 = (const float4*)sW1w;
    const float4* b4 = (const float4*)sW1b;

    #pragma unroll 2
    for (int k = 0; k < 128; k++) {
        float4 w  = w4[k];
        float4 be = b4[k];
        u64 c[10];
        {
            const ulonglong2* crow = (const ulonglong2*)(sW2Hp + k*20);
            #pragma unroll
            for (int q = 0; q < 5; q++) {
                ulonglong2 v = crow[q];
                c[2*q] = v.x; c[2*q+1] = v.y;
            }
        }
        float beArr[4] = {be.x, be.y, be.z, be.w};
        #pragma unroll
        for (int e = 0; e < 4; e++) {
            float xA = fmaxf(fmaf(w.x, curA[3*e], fmaf(w.y, curA[3*e+1],
                             fmaf(w.z, curA[3*e+2], beArr[e]))), 0.f);
            float xB = fmaxf(fmaf(w.x, curB[3*e], fmaf(w.y, curB[3*e+1],
                             fmaf(w.z, curB[3*e+2], beArr[e]))), 0.f);
            u64 dA = f2dup(xA);
            u64 dB = f2dup(xB);
            #pragma unroll
            for (int q = 0; q < 10; q++) {
                acc[2*e  ][q] = f2fma(c[q], dA, acc[2*e  ][q]);
                acc[2*e+1][q] = f2fma(c[q], dB, acc[2*e+1][q]);
            }
        }
    }

    // per-edge relu, sum over edges
    #pragma unroll
    for (int q = 0; q < 10; q++) {
        float loA = 0.f, hiA = 0.f, loB = 0.f, hiB = 0.f;
        #pragma unroll
        for (int e = 0; e < 4; e++) {
            float2 uA = f2unpack(acc[2*e  ][q]);
            float2 uB = f2unpack(acc[2*e+1][q]);
            loA += fmaxf(uA.x, 0.f); hiA += fmaxf(uA.y, 0.f);
            loB += fmaxf(uB.x, 0.f); hiB += fmaxf(uB.y, 0.f);
        }
        msA[q] = f2pack(loA, hiA);
        msB[q] = f2pack(loB, hiB);
    }
}

__global__ __launch_bounds__(NTHREADS, 1)
void vae_kernel(const float* __restrict__ initial_c,
                const float* __restrict__ current_c,
                const float* __restrict__ eps,
                const float* __restrict__ W1, const float* __restrict__ b1,
                const float* __restrict__ W2, const float* __restrict__ b2,
                const float* __restrict__ W3, const float* __restrict__ b3,
                const float* __restrict__ Wm, const float* __restrict__ bm,
                const float* __restrict__ Wv, const float* __restrict__ bv,
                const float* __restrict__ Wd1, const float* __restrict__ bd1,
                const float* __restrict__ Wd2, const float* __restrict__ bd2,
                float* __restrict__ out)
{
    extern __shared__ float sm[];
    float* sW1w = sm + OFF_W1W;
    float* sW1b = sm + OFF_W1B;
    float* sW2H = sm + OFF_W2H;
    float* sW3  = sm + OFF_W3;
    float* sWmv = sm + OFF_WMV;
    float* sWd1 = sm + OFF_WD1;
    float* sWd2 = sm + OFF_WD2;
    float* sBmv = sm + OFF_BMV;
    float* sBd2 = sm + OFF_BD2;
    float* sB2  = sm + OFF_B2;
    u64*   sMS  = (u64*)(sm + OFF_MS);

    const int t = threadIdx.x;

    // ---- pack weights into shared ----
    for (int o = t; o < 128; o += NTHREADS) {
        sW1w[o*4+0] = __ldg(&W1[o*13 + 10]);
        sW1w[o*4+1] = __ldg(&W1[o*13 + 11]);
        sW1w[o*4+2] = __ldg(&W1[o*13 + 12]);
        sW1w[o*4+3] = 0.f;
        float bb = __ldg(&b1[o]) + __ldg(&W1[o*13 + 0]);
        #pragma unroll
        for (int e = 0; e < 4; e++)
            sW1b[o*4+e] = bb + __ldg(&W1[o*13 + 6 + e]);
    }
    for (int i = t; i < 2*128*20; i += NTHREADS) {
        int p = i / (128*20);
        int r = i % (128*20);
        int k = r / 20, j = r % 20;
        int jj = 20*p + j;
        sW2H[i] = (jj < 39) ? __ldg(&W2[jj*128 + k]) : 0.f;
    }
    for (int i = t; i < 128*40; i += NTHREADS) {
        int j = i / 40, k = i % 40;
        sW3[i] = (k < 39) ? __ldg(&W3[j*39 + k]) : __ldg(&b3[j]);
    }
    for (int i = t; i < 128*16; i += NTHREADS) {
        int j = i / 16, q = i % 16;
        sWmv[i] = (q < 8) ? __ldg(&Wm[q*128 + j]) : __ldg(&Wv[(q-8)*128 + j]);
    }
    for (int i = t; i < 32*24; i += NTHREADS) {
        int h = i / 24, q = i % 24;
        float v;
        if (q < 12)       v = __ldg(&Wd1[h*25 + 5 + q]);
        else if (q < 20)  v = __ldg(&Wd1[h*25 + 17 + (q-12)]);
        else if (q == 20) v = __ldg(&bd1[h]) + __ldg(&Wd1[h*25 + 0]);
        else              v = 0.f;
        sWd1[i] = v;
    }
    for (int i = t; i < 32*12; i += NTHREADS) {
        int h = i / 12, j = i % 12;
        sWd2[i] = __ldg(&Wd2[j*32 + h]);
    }
    if (t < 16) sBmv[t] = (t < 8) ? __ldg(&bm[t]) : __ldg(&bv[t-8]);
    if (t < 12) sBd2[t] = __ldg(&bd2[t]);
    if (t < 40) sB2[t]  = (t < 39) ? __ldg(&b2[t]) : 0.f;
    __syncthreads();

    const int b0 = blockIdx.x * NTHREADS + t;
    const int b1i = b0 + HALF_B;
    const float* cc0 = current_c + (size_t)b0  * 30;
    const float* cc1 = current_c + (size_t)b1i * 30;

    float curA[12], curB[12];
    #pragma unroll
    for (int e = 0; e < 4; e++) {
        curA[3*e+0] = __ldg(&cc0[e]);
        curA[3*e+1] = __ldg(&cc0[10 + e]);
        curA[3*e+2] = __ldg(&cc0[14 + 4*e]);
        curB[3*e+0] = __ldg(&cc1[e]);
        curB[3*e+1] = __ldg(&cc1[10 + e]);
        curB[3*e+2] = __ldg(&cc1[14 + 4*e]);
    }

    // ---- message stage: pass 0 (j 0..19), park halves in scratch ----
    {
        u64 mA[10], mB[10];
        message_half(sW1w, sW1b, sW2H, sB2, curA, curB, mA, mB);
        #pragma unroll
        for (int q = 0; q < 10; q++) {
            sMS[q*NTHREADS + t]      = mA[q];
            sMS[(10+q)*NTHREADS + t] = mB[q];
        }
    }

    // ---- message stage: pass 1 (j 20..39), keep in regs ----
    u64 ms0[20], ms1[20];
    message_half(sW1w, sW1b, sW2H + 128*20, sB2 + 20, curA, curB, ms0 + 10, ms1 + 10);

    #pragma unroll
    for (int q = 0; q < 10; q++) {
        ms0[q] = sMS[q*NTHREADS + t];
        ms1[q] = sMS[(10+q)*NTHREADS + t];
    }
    // bias trick: element 39 pairs with W3 row's [39] = b3[j]
    {
        float2 v0 = f2unpack(ms0[19]);
        float2 v1 = f2unpack(ms1[19]);
        ms0[19] = f2pack(v0.x, 1.0f);
        ms1[19] = f2pack(v1.x, 1.0f);
    }

    // ---- readout: 39(+1) -> 128 relu -> means/log_var, weights shared ----
    u64 mv0[8], mv1[8];
    {
        const ulonglong2* bb = (const ulonglong2*)sBmv;
        #pragma unroll
        for (int q = 0; q < 4; q++) {
            ulonglong2 v = bb[q];
            mv0[2*q] = v.x; mv0[2*q+1] = v.y;
            mv1[2*q] = v.x; mv1[2*q+1] = v.y;
        }
    }

    #pragma unroll 2
    for (int j = 0; j < 128; j++) {
        const ulonglong2* w3r = (const ulonglong2*)(sW3 + j*40);
        u64 s0 = 0ULL, s1 = 0ULL, r0 = 0ULL, r1 = 0ULL;
        #pragma unroll
        for (int q = 0; q < 10; q += 2) {
            ulonglong2 c0 = w3r[q];
            ulonglong2 c1 = w3r[q+1];
            s0 = f2fma(c0.x, ms0[2*q],   s0);
            s1 = f2fma(c0.y, ms0[2*q+1], s1);
            s0 = f2fma(c1.x, ms0[2*q+2], s0);
            s1 = f2fma(c1.y, ms0[2*q+3], s1);
            r0 = f2fma(c0.x, ms1[2*q],   r0);
            r1 = f2fma(c0.y, ms1[2*q+1], r1);
            r0 = f2fma(c1.x, ms1[2*q+2], r0);
            r1 = f2fma(c1.y, ms1[2*q+3], r1);
        }
        float2 uA = f2unpack(f2add(s0, s1));
        float2 uB = f2unpack(f2add(r0, r1));
        float x3A = fmaxf(uA.x + uA.y, 0.f);
        float x3B = fmaxf(uB.x + uB.y, 0.f);
        u64 xpA = f2dup(x3A);
        u64 xpB = f2dup(x3B);
        const ulonglong2* wm = (const ulonglong2*)(sWmv + j*16);
        #pragma unroll
        for (int q = 0; q < 4; q++) {
            ulonglong2 c = wm[q];
            mv0[2*q]   = f2fma(c.x, xpA, mv0[2*q]);
            mv0[2*q+1] = f2fma(c.y, xpA, mv0[2*q+1]);
            mv1[2*q]   = f2fma(c.x, xpB, mv1[2*q]);
            mv1[2*q+1] = f2fma(c.y, xpB, mv1[2*q+1]);
        }
    }

    // ---- reparameterization ----
    float mvsA[16], mvsB[16];
    #pragma unroll
    for (int q = 0; q < 8; q++) {
        float2 vA = f2unpack(mv0[q]);
        float2 vB = f2unpack(mv1[q]);
        mvsA[2*q] = vA.x; mvsA[2*q+1] = vA.y;
        mvsB[2*q] = vB.x; mvsB[2*q+1] = vB.y;
    }
    float zvA[8], zvB[8];
    {
        const float4* epv = (const float4*)(eps + (size_t)b0 * 8);
        float4 e0 = epv[0], e1 = epv[1];
        float ev[8] = {e0.x, e0.y, e0.z, e0.w, e1.x, e1.y, e1.z, e1.w};
        #pragma unroll
        for (int i = 0; i < 8; i++)
            zvA[i] = fmaf(ev[i], __expf(0.5f * mvsA[8+i]), mvsA[i]);
    }
    {
        const float4* epv = (const float4*)(eps + (size_t)b1i * 8);
        float4 e0 = epv[0], e1 = epv[1];
        float ev[8] = {e0.x, e0.y, e0.z, e0.w, e1.x, e1.y, e1.z, e1.w};
        #pragma unroll
        for (int i = 0; i < 8; i++)
            zvB[i] = fmaf(ev[i], __expf(0.5f * mvsB[8+i]), mvsB[i]);
    }

    // ---- decoder: weights shared between both elements ----
    const float* ic0 = initial_c + (size_t)b0  * 30;
    const float* ic1 = initial_c + (size_t)b1i * 30;
    u64 dA[12], dB[12];
    dA[0] = f2pack(__ldg(&ic0[0]),  __ldg(&ic0[1]));
    dA[1] = f2pack(__ldg(&ic0[2]),  __ldg(&ic0[3]));
    dA[2] = f2pack(__ldg(&ic0[10]), __ldg(&ic0[11]));
    dA[3] = f2pack(__ldg(&ic0[12]), __ldg(&ic0[13]));
    dA[4] = f2pack(__ldg(&ic0[14]), __ldg(&ic0[18]));
    dA[5] = f2pack(__ldg(&ic0[22]), __ldg(&ic0[26]));
    dA[6] = f2pack(zvA[0], zvA[1]);
    dA[7] = f2pack(zvA[2], zvA[3]);
    dA[8] = f2pack(zvA[4], zvA[5]);
    dA[9] = f2pack(zvA[6], zvA[7]);
    dA[10] = f2pack(1.f, 0.f);
    dA[11] = 0ULL;
    dB[0] = f2pack(__ldg(&ic1[0]),  __ldg(&ic1[1]));
    dB[1] = f2pack(__ldg(&ic1[2]),  __ldg(&ic1[3]));
    dB[2] = f2pack(__ldg(&ic1[10]), __ldg(&ic1[11]));
    dB[3] = f2pack(__ldg(&ic1[12]), __ldg(&ic1[13]));
    dB[4] = f2pack(__ldg(&ic1[14]), __ldg(&ic1[18]));
    dB[5] = f2pack(__ldg(&ic1[22]), __ldg(&ic1[26]));
    dB[6] = f2pack(zvB[0], zvB[1]);
    dB[7] = f2pack(zvB[2], zvB[3]);
    dB[8] = f2pack(zvB[4], zvB[5]);
    dB[9] = f2pack(zvB[6], zvB[7]);
    dB[10] = f2pack(1.f, 0.f);
    dB[11] = 0ULL;

    u64 rA[6], rB[6];
    {
        const ulonglong2* bb = (const ulonglong2*)sBd2;
        #pragma unroll
        for (int q = 0; q < 3; q++) {
            ulonglong2 v = bb[q];
            rA[2*q] = v.x; rA[2*q+1] = v.y;
            rB[2*q] = v.x; rB[2*q+1] = v.y;
        }
    }

    #pragma unroll 4
    for (int h = 0; h < 32; h++) {
        const ulonglong2* w1r = (const ulonglong2*)(sWd1 + h*24);
        u64 t0 = 0ULL, t1 = 0ULL, u0 = 0ULL, u1 = 0ULL;
        #pragma unroll
        for (int q = 0; q < 6; q += 2) {
            ulonglong2 c0 = w1r[q];
            ulonglong2 c1 = w1r[q+1];
            t0 = f2fma(c0.x, dA[2*q],   t0);
            t1 = f2fma(c0.y, dA[2*q+1], t1);
            t0 = f2fma(c1.x, dA[2*q+2], t0);
            t1 = f2fma(c1.y, dA[2*q+3], t1);
            u0 = f2fma(c0.x, dB[2*q],   u0);
            u1 = f2fma(c0.y, dB[2*q+1], u1);
            u0 = f2fma(c1.x, dB[2*q+2], u0);
            u1 = f2fma(c1.y, dB[2*q+3], u1);
        }
        float2 sA = f2unpack(f2add(t0, t1));
        float2 sB = f2unpack(f2add(u0, u1));
        float hvA = fmaxf(sA.x + sA.y, 0.f);
        float hvB = fmaxf(sB.x + sB.y, 0.f);
        u64 hpA = f2dup(hvA);
        u64 hpB = f2dup(hvB);
        const ulonglong2* w2r = (const ulonglong2*)(sWd2 + h*12);
        #pragma unroll
        for (int q = 0; q < 3; q++) {
            ulonglong2 c = w2r[q];
            rA[2*q]   = f2fma(c.x, hpA, rA[2*q]);
            rA[2*q+1] = f2fma(c.y, hpA, rA[2*q+1]);
            rB[2*q]   = f2fma(c.x, hpB, rB[2*q]);
            rB[2*q+1] = f2fma(c.y, hpB, rB[2*q+1]);
        }
    }

    // ---- stores: recon_x [B,12] | means [B,8] | log_var [B,8] | z [B,8] ----
    {
        float rr[12];
        #pragma unroll
        for (int q = 0; q < 6; q++) {
            float2 v = f2unpack(rA[q]);
            rr[2*q] = v.x; rr[2*q+1] = v.y;
        }
        float* out_rec = out + (size_t)b0 * 12;
        #pragma unroll
        for (int ii = 0; ii < 3; ii++) {
            float4 v;
            v.x = __fdividef(1.f, 1.f + __expf(-rr[ii*4+0]));
            v.y = __fdividef(1.f, 1.f + __expf(-rr[ii*4+1]));
            v.z = __fdividef(1.f, 1.f + __expf(-rr[ii*4+2]));
            v.w = __fdividef(1.f, 1.f + __expf(-rr[ii*4+3]));
            ((float4*)out_rec)[ii] = v;
        }
        float* out_mean = out + (size_t)12*BATCH + (size_t)b0*8;
        ((float4*)out_mean)[0] = make_float4(mvsA[0], mvsA[1], mvsA[2], mvsA[3]);
        ((float4*)out_mean)[1] = make_float4(mvsA[4], mvsA[5], mvsA[6], mvsA[7]);
        float* out_lv = out + (size_t)20*BATCH + (size_t)b0*8;
        ((float4*)out_lv)[0] = make_float4(mvsA[8],  mvsA[9],  mvsA[10], mvsA[11]);
        ((float4*)out_lv)[1] = make_float4(mvsA[12], mvsA[13], mvsA[14], mvsA[15]);
        float* out_z = out + (size_t)28*BATCH + (size_t)b0*8;
        ((float4*)out_z)[0] = make_float4(zvA[0], zvA[1], zvA[2], zvA[3]);
        ((float4*)out_z)[1] = make_float4(zvA[4], zvA[5], zvA[6], zvA[7]);
    }
    {
        float rr[12];
        #pragma unroll
        for (int q = 0; q < 6; q++) {
            float2 v = f2unpack(rB[q]);
            rr[2*q] = v.x; rr[2*q+1] = v.y;
        }
        float* out_rec = out + (size_t)b1i * 12;
        #pragma unroll
        for (int ii = 0; ii < 3; ii++) {
            float4 v;
            v.x = __fdividef(1.f, 1.f + __expf(-rr[ii*4+0]));
            v.y = __fdividef(1.f, 1.f + __expf(-rr[ii*4+1]));
            v.z = __fdividef(1.f, 1.f + __expf(-rr[ii*4+2]));
            v.w = __fdividef(1.f, 1.f + __expf(-rr[ii*4+3]));
            ((float4*)out_rec)[ii] = v;
        }
        float* out_mean = out + (size_t)12*BATCH + (size_t)b1i*8;
        ((float4*)out_mean)[0] = make_float4(mvsB[0], mvsB[1], mvsB[2], mvsB[3]);
        ((float4*)out_mean)[1] = make_float4(mvsB[4], mvsB[5], mvsB[6], mvsB[7]);
        float* out_lv = out + (size_t)20*BATCH + (size_t)b1i*8;
        ((float4*)out_lv)[0] = make_float4(mvsB[8],  mvsB[9],  mvsB[10], mvsB[11]);
        ((float4*)out_lv)[1] = make_float4(mvsB[12], mvsB[13], mvsB[14], mvsB[15]);
        float* out_z = out + (size_t)28*BATCH + (size_t)b1i*8;
        ((float4*)out_z)[0] = make_float4(zvB[0], zvB[1], zvB[2], zvB[3]);
        ((float4*)out_z)[1] = make_float4(zvB[4], zvB[5], zvB[6], zvB[7]);
    }
}

extern "C" void kernel_launch(void* const* d_in, const int* in_sizes, int n_in,
                              void* d_out, int out_size)
{
    const float* initial_c = (const float*)d_in[0];
    // d_in[1] = initial_s (unused)
    const float* current_c = (const float*)d_in[2];
    const float* eps       = (const float*)d_in[3];
    const float* W1  = (const float*)d_in[4];
    const float* b1  = (const float*)d_in[5];
    const float* W2  = (const float*)d_in[6];
    const float* b2  = (const float*)d_in[7];
    const float* W3  = (const float*)d_in[8];
    const float* b3  = (const float*)d_in[9];
    const float* Wm  = (const float*)d_in[10];
    const float* bm  = (const float*)d_in[11];
    const float* Wv  = (const float*)d_in[12];
    const float* bv  = (const float*)d_in[13];
    const float* Wd1 = (const float*)d_in[14];
    const float* bd1 = (const float*)d_in[15];
    const float* Wd2 = (const float*)d_in[16];
    const float* bd2 = (const float*)d_in[17];
    float* out = (float*)d_out;

    cudaFuncSetAttribute(vae_kernel, cudaFuncAttributeMaxDynamicSharedMemorySize, SMEM_BYTES);
    vae_kernel<<<HALF_B / NTHREADS, NTHREADS, SMEM_BYTES>>>(
        initial_c, current_c, eps,
        W1, b1, W2, b2, W3, b3, Wm, bm, Wv, bv, Wd1, bd1, Wd2, bd2,
        out);
}

// round 8
// speedup vs baseline: 1.2461x; 1.0612x over previous
#include <cuda_runtime.h>
#include <cuda_bf16.h>
#include <math.h>

// ContextVAE: message-stage GEMM (x1 @ W2^T) on tensor cores via 3xTF32
// mma.sync.m16n8k8; x1 computed scalar into A-fragment layout; edge-sum via
// shfl; readout/decoder on packed-f32x2 scalar path (1 elem/thread).

#define BATCH 262144
#define NT 256
#define EPB 256   // elements per block

typedef unsigned long long u64;
typedef unsigned int u32;

__device__ __forceinline__ u64 f2fma(u64 a, u64 b, u64 c) {
    u64 d;
    asm("fma.rn.f32x2 %0, %1, %2, %3;" : "=l"(d) : "l"(a), "l"(b), "l"(c));
    return d;
}
__device__ __forceinline__ u64 f2add(u64 a, u64 b) {
    u64 d;
    asm("add.rn.f32x2 %0, %1, %2;" : "=l"(d) : "l"(a), "l"(b));
    return d;
}
__device__ __forceinline__ u64 f2pack(float lo, float hi) {
    u64 r;
    asm("mov.b64 %0, {%1, %2};" : "=l"(r) : "f"(lo), "f"(hi));
    return r;
}
__device__ __forceinline__ u64 f2dup(float v) {
    u64 r;
    asm("mov.b64 %0, {%1, %1};" : "=l"(r) : "f"(v));
    return r;
}
__device__ __forceinline__ float2 f2unpack(u64 p) {
    float2 r;
    asm("mov.b64 {%0, %1}, %2;" : "=f"(r.x), "=f"(r.y) : "l"(p));
    return r;
}
__device__ __forceinline__ u32 f2tf32(float x) {
    u32 r;
    asm("cvt.rna.tf32.f32 %0, %1;" : "=r"(r) : "f"(x));
    return r;
}
__device__ __forceinline__ void mma_tf32(float* d, const u32* a, const u32* b) {
    asm("mma.sync.aligned.m16n8k8.row.col.f32.tf32.tf32.f32 "
        "{%0,%1,%2,%3}, {%4,%5,%6,%7}, {%8,%9}, {%0,%1,%2,%3};"
        : "+f"(d[0]), "+f"(d[1]), "+f"(d[2]), "+f"(d[3])
        : "r"(a[0]), "r"(a[1]), "r"(a[2]), "r"(a[3]), "r"(b[0]), "r"(b[1]));
}

// Shared layout (floats):
#define OFF_W1W  0                       // [128]{w10,w11,w12,0}
#define OFF_W1B  (OFF_W1W + 128*4)       // [128][4 edges] bias
#define OFF_W2HI (OFF_W1B + 128*4)       // [128 k][40 n] tf32-hi
#define OFF_W2LO (OFF_W2HI + 128*40)     // [128 k][40 n] tf32-lo
#define OFF_W3   (OFF_W2LO + 128*40)     // [128 j][40] (k39 = b3)
#define OFF_WMV  (OFF_W3  + 128*40)      // [128 j][16]
#define OFF_WD1  (OFF_WMV + 128*16)      // [32][24]
#define OFF_WD2  (OFF_WD1 + 32*24)       // [32][12]
#define OFF_BMV  (OFF_WD2 + 32*12)       // [16]
#define OFF_BD2  (OFF_BMV + 16)          // [12]
#define OFF_B2   (OFF_BD2 + 12)          // [40] (b2, pad 0)
#define OFF_CUR  (OFF_B2 + 40)           // [256 elems][12]
#define OFF_MSUM (OFF_CUR + 256*12)      // [256 elems][44] padded
#define SMEM_FLOATS (OFF_MSUM + 256*44)
#define SMEM_BYTES  (SMEM_FLOATS * 4)

__global__ __launch_bounds__(NT, 1)
void vae_kernel(const float* __restrict__ initial_c,
                const float* __restrict__ current_c,
                const float* __restrict__ eps,
                const float* __restrict__ W1, const float* __restrict__ b1,
                const float* __restrict__ W2, const float* __restrict__ b2,
                const float* __restrict__ W3, const float* __restrict__ b3,
                const float* __restrict__ Wm, const float* __restrict__ bm,
                const float* __restrict__ Wv, const float* __restrict__ bv,
                const float* __restrict__ Wd1, const float* __restrict__ bd1,
                const float* __restrict__ Wd2, const float* __restrict__ bd2,
                float* __restrict__ out)
{
    extern __shared__ float sm[];
    float* sW1w  = sm + OFF_W1W;
    float* sW1b  = sm + OFF_W1B;
    float* sW2hi = sm + OFF_W2HI;
    float* sW2lo = sm + OFF_W2LO;
    float* sW3   = sm + OFF_W3;
    float* sWmv  = sm + OFF_WMV;
    float* sWd1  = sm + OFF_WD1;
    float* sWd2  = sm + OFF_WD2;
    float* sBmv  = sm + OFF_BMV;
    float* sBd2  = sm + OFF_BD2;
    float* sB2   = sm + OFF_B2;
    float* sCur  = sm + OFF_CUR;
    float* sMsum = sm + OFF_MSUM;

    const int t = threadIdx.x;

    // ---- stage weights ----
    for (int o = t; o < 128; o += NT) {
        sW1w[o*4+0] = __ldg(&W1[o*13 + 10]);
        sW1w[o*4+1] = __ldg(&W1[o*13 + 11]);
        sW1w[o*4+2] = __ldg(&W1[o*13 + 12]);
        sW1w[o*4+3] = 0.f;
        float bb = __ldg(&b1[o]) + __ldg(&W1[o*13 + 0]);
        #pragma unroll
        for (int e = 0; e < 4; e++)
            sW1b[o*4+e] = bb + __ldg(&W1[o*13 + 6 + e]);
    }
    for (int i = t; i < 128*40; i += NT) {
        int k = i / 40, j = i % 40;
        float w = (j < 39) ? __ldg(&W2[j*128 + k]) : 0.f;
        float hi = __uint_as_float(f2tf32(w));
        sW2hi[i] = hi;
        sW2lo[i] = __uint_as_float(f2tf32(w - hi));
    }
    for (int i = t; i < 128*40; i += NT) {
        int j = i / 40, k = i % 40;
        sW3[i] = (k < 39) ? __ldg(&W3[j*39 + k]) : __ldg(&b3[j]);
    }
    for (int i = t; i < 128*16; i += NT) {
        int j = i / 16, q = i % 16;
        sWmv[i] = (q < 8) ? __ldg(&Wm[q*128 + j]) : __ldg(&Wv[(q-8)*128 + j]);
    }
    for (int i = t; i < 32*24; i += NT) {
        int h = i / 24, q = i % 24;
        float v;
        if (q < 12)       v = __ldg(&Wd1[h*25 + 5 + q]);
        else if (q < 20)  v = __ldg(&Wd1[h*25 + 17 + (q-12)]);
        else if (q == 20) v = __ldg(&bd1[h]) + __ldg(&Wd1[h*25 + 0]);
        else              v = 0.f;
        sWd1[i] = v;
    }
    for (int i = t; i < 32*12; i += NT) {
        int h = i / 12, j = i % 12;
        sWd2[i] = __ldg(&Wd2[j*32 + h]);
    }
    if (t < 16) sBmv[t] = (t < 8) ? __ldg(&bm[t]) : __ldg(&bv[t-8]);
    if (t < 12) sBd2[t] = __ldg(&bd2[t]);
    if (t < 40) sB2[t]  = (t < 39) ? __ldg(&b2[t]) : 0.f;

    // ---- stage cur (predicate triplets) for this block's 256 elements ----
    {
        const int b = blockIdx.x * EPB + t;
        const float* cc = current_c + (size_t)b * 30;
        #pragma unroll
        for (int e = 0; e < 4; e++) {
            sCur[t*12 + 3*e + 0] = __ldg(&cc[e]);
            sCur[t*12 + 3*e + 1] = __ldg(&cc[10 + e]);
            sCur[t*12 + 3*e + 2] = __ldg(&cc[14 + 4*e]);
        }
    }
    __syncthreads();

    const int lane = t & 31;
    const int warp = t >> 5;
    const int r0   = lane >> 2;       // 0..7
    const int cIdx = lane & 3;        // 0..3
    const int edge = r0 & 3;          // fixed edge per thread

    // ===================== message stage on tensor cores =====================
    #pragma unroll 1
    for (int pass = 0; pass < 2; pass++) {
        const int elemBase = warp*32 + pass*16;

        // preload p-vectors for my 8 (elem,edge) slots
        float p[4][2][3];
        #pragma unroll
        for (int mt = 0; mt < 4; mt++)
            #pragma unroll
            for (int h = 0; h < 2; h++) {
                int e = elemBase + mt*4 + (r0 >> 2) + 2*h;
                p[mt][h][0] = sCur[e*12 + edge*3 + 0];
                p[mt][h][1] = sCur[e*12 + edge*3 + 1];
                p[mt][h][2] = sCur[e*12 + edge*3 + 2];
            }

        float acc[4][5][4];
        #pragma unroll
        for (int mt = 0; mt < 4; mt++)
            #pragma unroll
            for (int nt = 0; nt < 5; nt++)
                #pragma unroll
                for (int i = 0; i < 4; i++) acc[mt][nt][i] = 0.f;

        #pragma unroll 1
        for (int ks = 0; ks < 16; ks++) {
            const int c0 = ks*8 + cIdx;
            const int c1 = c0 + 4;
            float4 w0 = ((const float4*)sW1w)[c0];
            float4 w1 = ((const float4*)sW1w)[c1];
            float bias0 = sW1b[c0*4 + edge];
            float bias1 = sW1b[c1*4 + edge];

            // B fragments (hi & lo) for 5 n-tiles
            u32 bhi[5][2], blo[5][2];
            #pragma unroll
            for (int nt = 0; nt < 5; nt++) {
                int n = nt*8 + r0;
                bhi[nt][0] = __float_as_uint(sW2hi[c0*40 + n]);
                bhi[nt][1] = __float_as_uint(sW2hi[(c0+4)*40 + n]);
                blo[nt][0] = __float_as_uint(sW2lo[c0*40 + n]);
                blo[nt][1] = __float_as_uint(sW2lo[(c0+4)*40 + n]);
            }

            #pragma unroll
            for (int mt = 0; mt < 4; mt++) {
                float x00 = fmaxf(fmaf(w0.x, p[mt][0][0], fmaf(w0.y, p[mt][0][1],
                                  fmaf(w0.z, p[mt][0][2], bias0))), 0.f);
                float x10 = fmaxf(fmaf(w0.x, p[mt][1][0], fmaf(w0.y, p[mt][1][1],
                                  fmaf(w0.z, p[mt][1][2], bias0))), 0.f);
                float x01 = fmaxf(fmaf(w1.x, p[mt][0][0], fmaf(w1.y, p[mt][0][1],
                                  fmaf(w1.z, p[mt][0][2], bias1))), 0.f);
                float x11 = fmaxf(fmaf(w1.x, p[mt][1][0], fmaf(w1.y, p[mt][1][1],
                                  fmaf(w1.z, p[mt][1][2], bias1))), 0.f);
                u32 ahi[4], alo[4];
                ahi[0] = f2tf32(x00); ahi[1] = f2tf32(x10);
                ahi[2] = f2tf32(x01); ahi[3] = f2tf32(x11);
                alo[0] = f2tf32(x00 - __uint_as_float(ahi[0]));
                alo[1] = f2tf32(x10 - __uint_as_float(ahi[1]));
                alo[2] = f2tf32(x01 - __uint_as_float(ahi[2]));
                alo[3] = f2tf32(x11 - __uint_as_float(ahi[3]));
                #pragma unroll
                for (int nt = 0; nt < 5; nt++) {
                    mma_tf32(acc[mt][nt], ahi, bhi[nt]);
                    mma_tf32(acc[mt][nt], ahi, blo[nt]);
                    mma_tf32(acc[mt][nt], alo, bhi[nt]);
                }
            }
        }

        // epilogue: +b2, relu, sum over 4 edges (rows 4a..4a+3) via shfl
        #pragma unroll
        for (int mt = 0; mt < 4; mt++) {
            #pragma unroll
            for (int nt = 0; nt < 5; nt++) {
                int jb = nt*8 + cIdx*2;
                float2 b2v = *(const float2*)&sB2[jb];
                float v0 = fmaxf(acc[mt][nt][0] + b2v.x, 0.f);
                float v1 = fmaxf(acc[mt][nt][1] + b2v.y, 0.f);
                float v2 = fmaxf(acc[mt][nt][2] + b2v.x, 0.f);
                float v3 = fmaxf(acc[mt][nt][3] + b2v.y, 0.f);
                v0 += __shfl_xor_sync(0xffffffffu, v0, 4);
                v1 += __shfl_xor_sync(0xffffffffu, v1, 4);
                v2 += __shfl_xor_sync(0xffffffffu, v2, 4);
                v3 += __shfl_xor_sync(0xffffffffu, v3, 4);
                v0 += __shfl_xor_sync(0xffffffffu, v0, 8);
                v1 += __shfl_xor_sync(0xffffffffu, v1, 8);
                v2 += __shfl_xor_sync(0xffffffffu, v2, 8);
                v3 += __shfl_xor_sync(0xffffffffu, v3, 8);
                if (edge == 0) {
                    int eLo = elemBase + mt*4 + (r0 >> 2);
                    sMsum[eLo*44 + jb]     = v0;
                    sMsum[eLo*44 + jb + 1] = v1;
                    sMsum[(eLo+2)*44 + jb]     = v2;
                    sMsum[(eLo+2)*44 + jb + 1] = v3;
                }
            }
        }
    }
    __syncwarp();

    // ===================== readout + decoder (scalar f32x2, 1 elem/thread) ====
    const int b = blockIdx.x * EPB + t;

    u64 ms[20];
    #pragma unroll
    for (int q = 0; q < 20; q++) {
        float2 v = *(const float2*)&sMsum[t*44 + 2*q];
        ms[q] = f2pack(v.x, v.y);
    }
    { // bias trick: slot 39 multiplies W3 row's [39] = b3[j]
        float2 v = f2unpack(ms[19]);
        ms[19] = f2pack(v.x, 1.0f);
    }

    u64 mv[8];
    {
        const ulonglong2* bb = (const ulonglong2*)sBmv;
        #pragma unroll
        for (int q = 0; q < 4; q++) {
            ulonglong2 v = bb[q];
            mv[2*q] = v.x; mv[2*q+1] = v.y;
        }
    }

    #pragma unroll 2
    for (int j = 0; j < 128; j++) {
        const ulonglong2* w3r = (const ulonglong2*)(sW3 + j*40);
        u64 s0 = 0ULL, s1 = 0ULL, s2 = 0ULL, s3 = 0ULL;
        #pragma unroll
        for (int q = 0; q < 10; q += 2) {
            ulonglong2 cc0 = w3r[q];
            ulonglong2 cc1 = w3r[q+1];
            s0 = f2fma(cc0.x, ms[2*q],   s0);
            s1 = f2fma(cc0.y, ms[2*q+1], s1);
            s2 = f2fma(cc1.x, ms[2*q+2], s2);
            s3 = f2fma(cc1.y, ms[2*q+3], s3);
        }
        u64 st = f2add(f2add(s0, s2), f2add(s1, s3));
        float2 u = f2unpack(st);
        float x3 = fmaxf(u.x + u.y, 0.f);
        u64 xp = f2dup(x3);
        const ulonglong2* wm = (const ulonglong2*)(sWmv + j*16);
        #pragma unroll
        for (int q = 0; q < 4; q++) {
            ulonglong2 c = wm[q];
            mv[2*q]   = f2fma(c.x, xp, mv[2*q]);
            mv[2*q+1] = f2fma(c.y, xp, mv[2*q+1]);
        }
    }

    float mvs[16];
    #pragma unroll
    for (int q = 0; q < 8; q++) {
        float2 v = f2unpack(mv[q]);
        mvs[2*q] = v.x; mvs[2*q+1] = v.y;
    }
    const float4* epv = (const float4*)(eps + (size_t)b * 8);
    float4 e0 = epv[0], e1 = epv[1];
    float ev[8] = {e0.x, e0.y, e0.z, e0.w, e1.x, e1.y, e1.z, e1.w};
    float zv[8];
    #pragma unroll
    for (int i = 0; i < 8; i++)
        zv[i] = fmaf(ev[i], __expf(0.5f * mvs[8+i]), mvs[i]);

    const float* ic = initial_c + (size_t)b * 30;
    u64 d2[12];
    d2[0] = f2pack(__ldg(&ic[0]),  __ldg(&ic[1]));
    d2[1] = f2pack(__ldg(&ic[2]),  __ldg(&ic[3]));
    d2[2] = f2pack(__ldg(&ic[10]), __ldg(&ic[11]));
    d2[3] = f2pack(__ldg(&ic[12]), __ldg(&ic[13]));
    d2[4] = f2pack(__ldg(&ic[14]), __ldg(&ic[18]));
    d2[5] = f2pack(__ldg(&ic[22]), __ldg(&ic[26]));
    d2[6] = f2pack(zv[0], zv[1]);
    d2[7] = f2pack(zv[2], zv[3]);
    d2[8] = f2pack(zv[4], zv[5]);
    d2[9] = f2pack(zv[6], zv[7]);
    d2[10] = f2pack(1.f, 0.f);
    d2[11] = 0ULL;

    u64 r2[6];
    {
        const ulonglong2* bb = (const ulonglong2*)sBd2;
        #pragma unroll
        for (int q = 0; q < 3; q++) {
            ulonglong2 v = bb[q];
            r2[2*q] = v.x; r2[2*q+1] = v.y;
        }
    }

    #pragma unroll 4
    for (int h = 0; h < 32; h++) {
        const ulonglong2* w1r = (const ulonglong2*)(sWd1 + h*24);
        u64 t0 = 0ULL, t1 = 0ULL, t2 = 0ULL, t3 = 0ULL;
        #pragma unroll
        for (int q = 0; q < 6; q += 2) {
            ulonglong2 cc0 = w1r[q];
            ulonglong2 cc1 = w1r[q+1];
            t0 = f2fma(cc0.x, d2[2*q],   t0);
            t1 = f2fma(cc0.y, d2[2*q+1], t1);
            t2 = f2fma(cc1.x, d2[2*q+2], t2);
            t3 = f2fma(cc1.y, d2[2*q+3], t3);
        }
        u64 st = f2add(f2add(t0, t2), f2add(t1, t3));
        float2 u = f2unpack(st);
        float hv = fmaxf(u.x + u.y, 0.f);
        u64 hp = f2dup(hv);
        const ulonglong2* w2r = (const ulonglong2*)(sWd2 + h*12);
        #pragma unroll
        for (int q = 0; q < 3; q++) {
            ulonglong2 c = w2r[q];
            r2[2*q]   = f2fma(c.x, hp, r2[2*q]);
            r2[2*q+1] = f2fma(c.y, hp, r2[2*q+1]);
        }
    }

    // ---- stores: recon_x [B,12] | means [B,8] | log_var [B,8] | z [B,8] ----
    float rr[12];
    #pragma unroll
    for (int q = 0; q < 6; q++) {
        float2 v = f2unpack(r2[q]);
        rr[2*q] = v.x; rr[2*q+1] = v.y;
    }
    float* out_rec = out + (size_t)b * 12;
    #pragma unroll
    for (int ii = 0; ii < 3; ii++) {
        float4 v;
        v.x = __fdividef(1.f, 1.f + __expf(-rr[ii*4+0]));
        v.y = __fdividef(1.f, 1.f + __expf(-rr[ii*4+1]));
        v.z = __fdividef(1.f, 1.f + __expf(-rr[ii*4+2]));
        v.w = __fdividef(1.f, 1.f + __expf(-rr[ii*4+3]));
        ((float4*)out_rec)[ii] = v;
    }
    float* out_mean = out + (size_t)12*BATCH + (size_t)b*8;
    ((float4*)out_mean)[0] = make_float4(mvs[0], mvs[1], mvs[2], mvs[3]);
    ((float4*)out_mean)[1] = make_float4(mvs[4], mvs[5], mvs[6], mvs[7]);
    float* out_lv = out + (size_t)20*BATCH + (size_t)b*8;
    ((float4*)out_lv)[0] = make_float4(mvs[8],  mvs[9],  mvs[10], mvs[11]);
    ((float4*)out_lv)[1] = make_float4(mvs[12], mvs[13], mvs[14], mvs[15]);
    float* out_z = out + (size_t)28*BATCH + (size_t)b*8;
    ((float4*)out_z)[0] = make_float4(zv[0], zv[1], zv[2], zv[3]);
    ((float4*)out_z)[1] = make_float4(zv[4], zv[5], zv[6], zv[7]);
}

extern "C" void kernel_launch(void* const* d_in, const int* in_sizes, int n_in,
                              void* d_out, int out_size)
{
    const float* initial_c = (const float*)d_in[0];
    // d_in[1] = initial_s (unused)
    const float* current_c = (const float*)d_in[2];
    const float* eps       = (const float*)d_in[3];
    const float* W1  = (const float*)d_in[4];
    const float* b1  = (const float*)d_in[5];
    const float* W2  = (const float*)d_in[6];
    const float* b2  = (const float*)d_in[7];
    const float* W3  = (const float*)d_in[8];
    const float* b3  = (const float*)d_in[9];
    const float* Wm  = (const float*)d_in[10];
    const float* bm  = (const float*)d_in[11];
    const float* Wv  = (const float*)d_in[12];
    const float* bv  = (const float*)d_in[13];
    const float* Wd1 = (const float*)d_in[14];
    const float* bd1 = (const float*)d_in[15];
    const float* Wd2 = (const float*)d_in[16];
    const float* bd2 = (const float*)d_in[17];
    float* out = (float*)d_out;

    cudaFuncSetAttribute(vae_kernel, cudaFuncAttributeMaxDynamicSharedMemorySize, SMEM_BYTES);
    vae_kernel<<<BATCH / EPB, NT, SMEM_BYTES>>>(
        initial_c, current_c, eps,
        W1, b1, W2, b2, W3, b3, Wm, bm, Wv, bv, Wd1, bd1, Wd2, bd2,
        out);
}